// round 17
// baseline (speedup 1.0000x reference)
#include <cuda_runtime.h>

// LSTM autoencoder: B=4096, T=512, F=8, H=16.
// One 16-lane group per batch (2 groups/warp, 4 batches/block of 64 threads).
// Lane q owns h[q], c[q] and gate rows {q,16+q,32+q,48+q} (i,f,g,o).
// h allgather via double-buffered shared memory (STS + syncwarp + ld.shared.v2.f64),
// all dot products as fma.rn.f32x2 over (even,odd) packed pairs -> one horizontal
// add per gate. Zero packing MOVs: vector loads deliver the packed operands.

#define Tn 512

__device__ __forceinline__ float ex2f(float x){ float r; asm("ex2.approx.ftz.f32 %0,%1;" : "=f"(r) : "f"(x)); return r; }
__device__ __forceinline__ float rcpf(float x){ float r; asm("rcp.approx.ftz.f32 %0,%1;" : "=f"(r) : "f"(x)); return r; }
__device__ __forceinline__ float sigf(float x){
    // 1/(1+2^(-x*log2e)); saturates safely: ex2->inf => rcp->0, ex2->0 => 1
    return rcpf(1.0f + ex2f(-1.4426950408889634f * x));
}
__device__ __forceinline__ float tanhf_fast(float x){
    // tanh(x) = 2*sigmoid(2x)-1; inf-safe without clamps
    return fmaf(2.0f, rcpf(1.0f + ex2f(-2.8853900817779268f * x)), -1.0f);
}

__device__ __forceinline__ double pk2(float lo, float hi){
    double d; asm("mov.b64 %0, {%1, %2};" : "=d"(d) : "f"(lo), "f"(hi)); return d;
}
__device__ __forceinline__ void up2(double d, float& lo, float& hi){
    asm("mov.b64 {%0, %1}, %2;" : "=f"(lo), "=f"(hi) : "d"(d));
}
__device__ __forceinline__ double ffma2(double a, double b, double c){
    double r; asm("fma.rn.f32x2 %0, %1, %2, %3;" : "=d"(r) : "d"(a), "d"(b), "d"(c));
    return r;
}

__global__ void __launch_bounds__(64, 7)
lstm_ae_kernel(const float* __restrict__ x,
               const float* __restrict__ eWih, const float* __restrict__ eWhh,
               const float* __restrict__ ebih, const float* __restrict__ ebhh,
               const float* __restrict__ dWih, const float* __restrict__ dWhh,
               const float* __restrict__ dbih, const float* __restrict__ dbhh,
               const float* __restrict__ oW,   const float* __restrict__ obv,
               float* __restrict__ out)
{
    // [buffer][group][h] : group stride 64B keeps the two groups of a warp on
    // disjoint banks for both STS and LDS.128.
    __shared__ __align__(16) float hx[2][4][16];

    const int tid = threadIdx.x;
    const int q   = tid & 15;           // lane within 16-lane group
    const int grp = tid >> 4;           // 0..3 within block
    const int b   = blockIdx.x * 4 + grp;

    float* const hb0 = &hx[0][grp][0];  // buffer stride = 64 floats

    // ---------------- encoder weights (packed even/odd pairs) ----------------
    double whh[4][8], wih[4][4], bias2[4];
#pragma unroll
    for (int g = 0; g < 4; g++) {
        const float* wr = eWhh + (g * 16 + q) * 16;
#pragma unroll
        for (int k = 0; k < 8; k++) whh[g][k] = pk2(wr[2*k], wr[2*k+1]);
        const float* wi = eWih + (g * 16 + q) * 8;
#pragma unroll
        for (int k = 0; k < 4; k++) wih[g][k] = pk2(wi[2*k], wi[2*k+1]);
        bias2[g] = pk2(ebih[g*16 + q] + ebhh[g*16 + q], 0.0f);
    }

    // x row for this batch, viewed as packed (f32,f32) pairs: 2 double2 / step
    const double2* xb = reinterpret_cast<const double2*>(x + (size_t)b * (Tn * 8));

    float h = 0.0f, c = 0.0f;
    double2 xA = xb[0], xB = xb[1];

    // ---------------- encoder recurrence -------------------------------------
#pragma unroll 1
    for (int t = 0; t < Tn; t++) {
        float* hb = hb0 + ((t & 1) << 6);
        hb[q] = h;
        const int tn = (t + 1) & (Tn - 1);
        const double2 xAn = xb[2*tn], xBn = xb[2*tn + 1];   // prefetch next x
        __syncwarp();
        const double2* hp = reinterpret_cast<const double2*>(hb);
        const double2 h01 = hp[0], h23 = hp[1], h45 = hp[2], h67 = hp[3];

        float gate[4];
#pragma unroll
        for (int g = 0; g < 4; g++) {
            double a = bias2[g];
            a = ffma2(wih[g][0], xA.x, a);
            a = ffma2(wih[g][1], xA.y, a);
            a = ffma2(wih[g][2], xB.x, a);
            a = ffma2(wih[g][3], xB.y, a);
            a = ffma2(whh[g][0], h01.x, a);
            a = ffma2(whh[g][1], h01.y, a);
            a = ffma2(whh[g][2], h23.x, a);
            a = ffma2(whh[g][3], h23.y, a);
            a = ffma2(whh[g][4], h45.x, a);
            a = ffma2(whh[g][5], h45.y, a);
            a = ffma2(whh[g][6], h67.x, a);
            a = ffma2(whh[g][7], h67.y, a);
            float lo, hi; up2(a, lo, hi);
            gate[g] = lo + hi;
        }
        xA = xAn; xB = xBn;
        const float gi = sigf(gate[0]);
        const float gf = sigf(gate[1]);
        const float gg = tanhf_fast(gate[2]);
        const float go = sigf(gate[3]);
        c = fmaf(gf, c, gi * gg);
        h = go * tanhf_fast(c);
    }

    // ---------------- decoder setup: xp = dWih @ hT + biases -----------------
    // hT allgather through buffer 0 (safe: buf0 last read at t=510, all lanes
    // passed sync(511) which orders those reads before this store).
    hb0[q] = h;
    __syncwarp();
    {
        const double2* hp = reinterpret_cast<const double2*>(hb0);
        const double2 h01 = hp[0], h23 = hp[1], h45 = hp[2], h67 = hp[3];
        const double hpair[8] = {h01.x, h01.y, h23.x, h23.y, h45.x, h45.y, h67.x, h67.y};
#pragma unroll
        for (int g = 0; g < 4; g++) {
            const float* wr = dWih + (g*16 + q) * 16;
            double a = pk2(dbih[g*16 + q] + dbhh[g*16 + q], 0.0f);
#pragma unroll
            for (int k = 0; k < 8; k++)
                a = ffma2(pk2(wr[2*k], wr[2*k+1]), hpair[k], a);
            float lo, hi; up2(a, lo, hi);
            bias2[g] = pk2(lo + hi, 0.0f);          // reuse bias2 as xp constant
            const float* wd = dWhh + (g*16 + q) * 16;
#pragma unroll
            for (int k = 0; k < 8; k++) whh[g][k] = pk2(wd[2*k], wd[2*k+1]);
        }
    }
    // output projection weights: lane q (mod 8) owns output feature fo
    const int fo = q & 7;
    double wo[8];
#pragma unroll
    for (int k = 0; k < 8; k++) wo[k] = pk2(oW[fo*16 + 2*k], oW[fo*16 + 2*k + 1]);
    const double ob2 = pk2(obv[fo], 0.0f);

    float* const op = out + (size_t)b * (Tn * 8);
    h = 0.0f; c = 0.0f;

    // ---------------- decoder recurrence (fused output projection) -----------
    // Buffer parity flipped (t+1)&1 so t=0 uses buf1 (buf0 is still being read
    // by the prologue allgather on slow lanes).
#pragma unroll 1
    for (int t = 0; t < Tn; t++) {
        float* hb = hb0 + (((t + 1) & 1) << 6);
        hb[q] = h;
        __syncwarp();
        const double2* hp = reinterpret_cast<const double2*>(hb);
        const double2 h01 = hp[0], h23 = hp[1], h45 = hp[2], h67 = hp[3];

        // output for decoded[t-1] (h here is h_{t-1})
        double oa = ob2;
        oa = ffma2(wo[0], h01.x, oa);
        oa = ffma2(wo[1], h01.y, oa);
        oa = ffma2(wo[2], h23.x, oa);
        oa = ffma2(wo[3], h23.y, oa);
        oa = ffma2(wo[4], h45.x, oa);
        oa = ffma2(wo[5], h45.y, oa);
        oa = ffma2(wo[6], h67.x, oa);
        oa = ffma2(wo[7], h67.y, oa);
        float olo, ohi; up2(oa, olo, ohi);
        if (t > 0 && q < 8) op[(t - 1) * 8 + q] = olo + ohi;

        float gate[4];
#pragma unroll
        for (int g = 0; g < 4; g++) {
            double a = bias2[g];
            a = ffma2(whh[g][0], h01.x, a);
            a = ffma2(whh[g][1], h01.y, a);
            a = ffma2(whh[g][2], h23.x, a);
            a = ffma2(whh[g][3], h23.y, a);
            a = ffma2(whh[g][4], h45.x, a);
            a = ffma2(whh[g][5], h45.y, a);
            a = ffma2(whh[g][6], h67.x, a);
            a = ffma2(whh[g][7], h67.y, a);
            float lo, hi; up2(a, lo, hi);
            gate[g] = lo + hi;
        }
        const float gi = sigf(gate[0]);
        const float gf = sigf(gate[1]);
        const float gg = tanhf_fast(gate[2]);
        const float go = sigf(gate[3]);
        c = fmaf(gf, c, gi * gg);
        h = go * tanhf_fast(c);
    }

    // final output: decoded[T-1] = h after last step (exchange via buf1)
    {
        float* hb = hb0 + 64;   // parity (Tn+1)&1 == 1
        hb[q] = h;
        __syncwarp();
        const double2* hp = reinterpret_cast<const double2*>(hb);
        const double2 h01 = hp[0], h23 = hp[1], h45 = hp[2], h67 = hp[3];
        double oa = ob2;
        oa = ffma2(wo[0], h01.x, oa);
        oa = ffma2(wo[1], h01.y, oa);
        oa = ffma2(wo[2], h23.x, oa);
        oa = ffma2(wo[3], h23.y, oa);
        oa = ffma2(wo[4], h45.x, oa);
        oa = ffma2(wo[5], h45.y, oa);
        oa = ffma2(wo[6], h67.x, oa);
        oa = ffma2(wo[7], h67.y, oa);
        float olo, ohi; up2(oa, olo, ohi);
        if (q < 8) op[(Tn - 1) * 8 + q] = olo + ohi;
    }
}

extern "C" void kernel_launch(void* const* d_in, const int* in_sizes, int n_in,
                              void* d_out, int out_size)
{
    const float* x    = (const float*)d_in[0];
    const float* eWih = (const float*)d_in[1];
    const float* eWhh = (const float*)d_in[2];
    const float* ebih = (const float*)d_in[3];
    const float* ebhh = (const float*)d_in[4];
    const float* dWih = (const float*)d_in[5];
    const float* dWhh = (const float*)d_in[6];
    const float* dbih = (const float*)d_in[7];
    const float* dbhh = (const float*)d_in[8];
    const float* oW   = (const float*)d_in[9];
    const float* obv  = (const float*)d_in[10];
    float* out = (float*)d_out;

    // 4096 batches * 16 lanes = 65536 threads; 64-thread blocks -> 1024 blocks
    lstm_ae_kernel<<<1024, 64>>>(x, eWih, eWhh, ebih, ebhh,
                                 dWih, dWhh, dbih, dbhh, oW, obv, out);
}